// round 4
// baseline (speedup 1.0000x reference)
#include <cuda_runtime.h>
#include <cstdint>
#include <math.h>

// Problem constants (fixed by the reference)
#define NUM_K    1024      // primitives / codebook size
#define NUM_ROWS 32768     // 8 * 4096 tokens
#define DIM_D    1024      // embedding dim

#define TINY_F   1.17549435e-38f
#define LN2_F    0.693147180559945f
#define T_SMALL  4.1e-3f   // below this, force exact-path candidacy (MUFU rel err blows up)
#define CAND_EPS 3e-4f     // > 2x proven |z_approx - z_exact| bound for non-forced elems
#define NEG_INF  __int_as_float(0xff800000)

// persistent scratch; g_counts/g_done are self-resetting (last block restores zeros)
__device__ int g_counts[NUM_K];
__device__ unsigned int g_done = 0;

// ---------------------------------------------------------------------------
// Threefry-2x32, 20 rounds, key = (0, 42) (jax.random.key(42)).
// Partitionable-mode 32-bit harvest: counter=(0, elem_idx); out = x0 ^ x1.
// ---------------------------------------------------------------------------
__device__ __forceinline__ uint32_t threefry_xor(uint32_t c1) {
    const uint32_t ks0 = 0u;
    const uint32_t ks1 = 42u;
    const uint32_t ks2 = 0x1BD11BDAu ^ 0u ^ 42u;
    uint32_t x0 = 0u + ks0;
    uint32_t x1 = c1 + ks1;
#define TF_R(r) { x0 += x1; x1 = __funnelshift_l(x1, x1, (r)); x1 ^= x0; }
    TF_R(13) TF_R(15) TF_R(26) TF_R(6)
    x0 += ks1; x1 += ks2 + 1u;
    TF_R(17) TF_R(29) TF_R(16) TF_R(24)
    x0 += ks2; x1 += ks0 + 2u;
    TF_R(13) TF_R(15) TF_R(26) TF_R(6)
    x0 += ks0; x1 += ks1 + 3u;
    TF_R(17) TF_R(29) TF_R(16) TF_R(24)
    x0 += ks1; x1 += ks2 + 4u;
    TF_R(13) TF_R(15) TF_R(26) TF_R(6)
    x0 += ks2; x1 += ks0 + 5u;
#undef TF_R
    return x0 ^ x1;
}

// Exact gumbel: same formula/precision as XLA (accurate logf). u pre-clamped.
__device__ __forceinline__ float gumbel_exact(float u) {
    return -logf(-logf(u));
}

// ---------------------------------------------------------------------------
// One block per row, fully fused (single kernel per launch).
// Phase 1 (branch-free): MUFU-based z~ for all K; tiny-t elems get a clamped
//   lower bound + forced-candidate flag. Block max of z~.
// Phase 2: exact z (accurate logf) only for candidates; argmax over exact
//   values (lower-index tie-break). Gather primitives[idx]; atomic count.
// Epilogue: last finished block writes counts to out and re-zeroes scratch.
// ---------------------------------------------------------------------------
__global__ __launch_bounds__(256, 4)
void vybn_fused_kernel(const float* __restrict__ logits,
                       const float* __restrict__ prim,
                       float* __restrict__ out,
                       long long out_elems) {
    const int row  = blockIdx.x;
    const int t    = threadIdx.x;
    const int lane = t & 31;
    const int warp = t >> 5;

    // each thread handles k in [4t, 4t+4)
    const float4 lv = ((const float4*)(logits + (size_t)row * NUM_K))[t];
    const uint32_t base = (uint32_t)row * (uint32_t)NUM_K + (uint32_t)(4 * t);

    float u[4];        // clamped uniform, kept for the exact rescue path
    float za[4];       // z approx (lower bound for forced elements)
    unsigned fmask = 0;
    float zmax = NEG_INF;

    {
        const float lvi0 = lv.x, lvi1 = lv.y, lvi2 = lv.z, lvi3 = lv.w;
        #pragma unroll
        for (int i = 0; i < 4; i++) {
            uint32_t bits = threefry_xor(base + (uint32_t)i);
            float f = __uint_as_float((bits >> 9) | 0x3f800000u) - 1.0f;
            u[i] = fmaxf(f, TINY_F);
            // t~ = -ln(u) via MUFU.LG2 + FMUL
            float tt = __log2f(u[i]) * (-LN2_F);
            // force exact evaluation where MUFU relative error is unbounded
            fmask |= (tt < T_SMALL) ? (1u << i) : 0u;
            float ttc = fmaxf(tt, T_SMALL);        // clamped -> za is a lower bound there
            float l = (i == 0) ? lvi0 : (i == 1) ? lvi1 : (i == 2) ? lvi2 : lvi3;
            za[i] = fmaf(__log2f(ttc), -LN2_F, l);
            zmax = fmaxf(zmax, za[i]);
        }
    }

    // block max of z~
    #pragma unroll
    for (int off = 16; off > 0; off >>= 1)
        zmax = fmaxf(zmax, __shfl_xor_sync(0xFFFFFFFFu, zmax, off));

    __shared__ float swv[8];
    __shared__ float swe[8];
    __shared__ int   swi[8];
    __shared__ int   s_idx;
    __shared__ int   s_last;
    if (lane == 0) swv[warp] = zmax;
    __syncthreads();

    float gmax = swv[0];
    #pragma unroll
    for (int w = 1; w < 8; w++) gmax = fmaxf(gmax, swv[w]);
    const float thresh = gmax - CAND_EPS;

    // Phase 2: exact evaluation for candidates only (rare; logit reloaded via L1)
    float best = NEG_INF;
    int   bidx = 0x7FFFFFFF;
    #pragma unroll
    for (int i = 0; i < 4; i++) {
        if ((za[i] >= thresh) || ((fmask >> i) & 1u)) {
            float l  = __ldg(logits + (size_t)row * NUM_K + 4 * t + i);
            float ze = l + gumbel_exact(u[i]);
            if (ze > best) { best = ze; bidx = 4 * t + i; }
        }
    }

    // warp argmax (ties -> lower index)
    #pragma unroll
    for (int off = 16; off > 0; off >>= 1) {
        float ov = __shfl_down_sync(0xFFFFFFFFu, best, off);
        int   oi = __shfl_down_sync(0xFFFFFFFFu, bidx, off);
        if (ov > best || (ov == best && oi < bidx)) { best = ov; bidx = oi; }
    }
    if (lane == 0) { swe[warp] = best; swi[warp] = bidx; }
    __syncthreads();

    if (t == 0) {
        best = swe[0]; bidx = swi[0];
        #pragma unroll
        for (int w = 1; w < 8; w++) {
            float ov = swe[w]; int oi = swi[w];
            if (ov > best || (ov == best && oi < bidx)) { best = ov; bidx = oi; }
        }
        s_idx = bidx;
        atomicAdd(&g_counts[bidx], 1);
        long long ioff = (long long)NUM_ROWS * DIM_D + row;
        if (ioff < out_elems) out[ioff] = (float)bidx;
    }
    __syncthreads();

    const int idx = s_idx;
    // embeddings row = primitives[idx] exactly (hard one-hot forward)
    float4 v = ((const float4*)(prim + (size_t)idx * DIM_D))[t];
    ((float4*)(out + (size_t)row * DIM_D))[t] = v;

    // ---- last-block epilogue: write counts, reset scratch for next launch ----
    if (t == 0) {
        __threadfence();
        unsigned old = atomicAdd(&g_done, 1u);
        s_last = (old == (unsigned)(gridDim.x - 1)) ? 1 : 0;
    }
    __syncthreads();
    if (s_last) {
        __threadfence();
        #pragma unroll
        for (int k = t; k < NUM_K; k += 256) {
            long long off = (long long)NUM_ROWS * DIM_D + NUM_ROWS + k;
            if (off < out_elems) out[off] = (float)g_counts[k];
            g_counts[k] = 0;
        }
        __syncthreads();
        if (t == 0) atomicExch(&g_done, 0u);
    }
}

extern "C" void kernel_launch(void* const* d_in, const int* in_sizes, int n_in,
                              void* d_out, int out_size) {
    const float* logits = (const float*)d_in[0];
    const float* prim   = (const float*)d_in[1];
    if (n_in >= 2 && in_sizes[0] < in_sizes[1]) {
        const float* tmp = logits; logits = prim; prim = tmp;
    }
    float* out = (float*)d_out;

    vybn_fused_kernel<<<NUM_ROWS, 256>>>(logits, prim, out, (long long)out_size);
}

// round 5
// speedup vs baseline: 1.0038x; 1.0038x over previous
#include <cuda_runtime.h>
#include <cstdint>
#include <math.h>

// Problem constants (fixed by the reference)
#define NUM_K    1024      // primitives / codebook size
#define NUM_ROWS 32768     // 8 * 4096 tokens
#define DIM_D    1024      // embedding dim

#define TINY_F   1.17549435e-38f
#define LN2_F    0.693147180559945f
#define T_SMALL  4.1e-3f   // below this, force exact-path candidacy (MUFU rel err blows up)
#define CAND_EPS 3e-4f     // ~3x proven |z_approx - z_exact| bound for non-forced elems
#define NEG_INF  __int_as_float(0xff800000)

// scratch: activation counts (zeroed via cudaMemsetAsync each launch)
__device__ int g_counts[NUM_K];

// ---------------------------------------------------------------------------
// Threefry-2x32, 20 rounds, key = (0, 42) (jax.random.key(42)).
// Partitionable-mode 32-bit harvest: counter=(0, elem_idx); out = x0 ^ x1.
// ---------------------------------------------------------------------------
__device__ __forceinline__ uint32_t tf_rotl(uint32_t x, int r) {
    return (x << r) | (x >> (32 - r));   // ptxas folds to one SHF
}

__device__ __forceinline__ uint32_t threefry_xor(uint32_t c1) {
    const uint32_t ks0 = 0u;
    const uint32_t ks1 = 42u;
    const uint32_t ks2 = 0x1BD11BDAu ^ 0u ^ 42u;
    uint32_t x0 = 0u + ks0;
    uint32_t x1 = c1 + ks1;
#define TF_R(r) { x0 += x1; x1 = tf_rotl(x1, (r)); x1 ^= x0; }
    TF_R(13) TF_R(15) TF_R(26) TF_R(6)
    x0 += ks1; x1 += ks2 + 1u;
    TF_R(17) TF_R(29) TF_R(16) TF_R(24)
    x0 += ks2; x1 += ks0 + 2u;
    TF_R(13) TF_R(15) TF_R(26) TF_R(6)
    x0 += ks0; x1 += ks1 + 3u;
    TF_R(17) TF_R(29) TF_R(16) TF_R(24)
    x0 += ks1; x1 += ks2 + 4u;
    TF_R(13) TF_R(15) TF_R(26) TF_R(6)
    x0 += ks2; x1 += ks0 + 5u;
#undef TF_R
    return x0 ^ x1;
}

// Exact z: identical formula/precision to the reference (XLA lowers log ->
// libdevice logf = CUDA accurate logf). u must already be clamped.
// __noinline__: keeps the two accurate-logf bodies OUT of the hot loop so the
// phase-1 instruction stream fits the 6KB L0 I$. Called rarely (candidates).
__device__ __noinline__ float exact_z(float u, float l) {
    return l + (-logf(-logf(u)));
}

// ---------------------------------------------------------------------------
// One block per row.
// Phase 1 (branch-free, logf-free): MUFU-based z~ for all K; tiny-t elems get
//   a clamped lower bound + forced-candidate flag. Block max of z~.
// Phase 2: exact z (accurate logf, out-of-line) only for candidates within
//   CAND_EPS of the max; argmax over exact values (lower-index tie-break).
// Then gather primitives[idx] -> out, atomic count.
// ---------------------------------------------------------------------------
__global__ __launch_bounds__(256, 4)
void vybn_fused_kernel(const float* __restrict__ logits,
                       const float* __restrict__ prim,
                       float* __restrict__ out,
                       long long out_elems) {
    const int row  = blockIdx.x;
    const int t    = threadIdx.x;
    const int lane = t & 31;
    const int warp = t >> 5;

    // each thread handles k in [4t, 4t+4)
    const float4 lv = ((const float4*)(logits + (size_t)row * NUM_K))[t];
    const uint32_t base = (uint32_t)row * (uint32_t)NUM_K + (uint32_t)(4 * t);

    float u[4];        // clamped uniform, kept for the exact rescue path
    float za[4];       // z approx (lower bound for forced elements)
    unsigned fmask = 0;
    float zmax = NEG_INF;

    {
        const float lvi0 = lv.x, lvi1 = lv.y, lvi2 = lv.z, lvi3 = lv.w;
        #pragma unroll
        for (int i = 0; i < 4; i++) {
            uint32_t bits = threefry_xor(base + (uint32_t)i);
            float f = __uint_as_float((bits >> 9) | 0x3f800000u) - 1.0f;
            u[i] = fmaxf(f, TINY_F);
            // t~ = -ln(u) via MUFU.LG2 + FMUL
            float tt = __log2f(u[i]) * (-LN2_F);
            // force exact evaluation where MUFU relative error is unbounded
            fmask |= (tt < T_SMALL) ? (1u << i) : 0u;
            float ttc = fmaxf(tt, T_SMALL);        // clamped -> za is a lower bound there
            float l = (i == 0) ? lvi0 : (i == 1) ? lvi1 : (i == 2) ? lvi2 : lvi3;
            za[i] = fmaf(__log2f(ttc), -LN2_F, l);
            zmax = fmaxf(zmax, za[i]);
        }
    }

    // block max of z~
    #pragma unroll
    for (int off = 16; off > 0; off >>= 1)
        zmax = fmaxf(zmax, __shfl_xor_sync(0xFFFFFFFFu, zmax, off));

    __shared__ float swv[8];
    __shared__ float swe[8];
    __shared__ int   swi[8];
    __shared__ int   s_idx;
    if (lane == 0) swv[warp] = zmax;
    __syncthreads();

    float gmax = swv[0];
    #pragma unroll
    for (int w = 1; w < 8; w++) gmax = fmaxf(gmax, swv[w]);
    const float thresh = gmax - CAND_EPS;

    // Phase 2: exact evaluation for candidates only (rare; out-of-line logf)
    float best = NEG_INF;
    int   bidx = 0x7FFFFFFF;
    {
        const float lvi0 = lv.x, lvi1 = lv.y, lvi2 = lv.z, lvi3 = lv.w;
        #pragma unroll
        for (int i = 0; i < 4; i++) {
            if ((za[i] >= thresh) || ((fmask >> i) & 1u)) {
                float l  = (i == 0) ? lvi0 : (i == 1) ? lvi1 : (i == 2) ? lvi2 : lvi3;
                float ze = exact_z(u[i], l);
                if (ze > best) { best = ze; bidx = 4 * t + i; }
            }
        }
    }

    // warp argmax (ties -> lower index)
    #pragma unroll
    for (int off = 16; off > 0; off >>= 1) {
        float ov = __shfl_down_sync(0xFFFFFFFFu, best, off);
        int   oi = __shfl_down_sync(0xFFFFFFFFu, bidx, off);
        if (ov > best || (ov == best && oi < bidx)) { best = ov; bidx = oi; }
    }
    if (lane == 0) { swe[warp] = best; swi[warp] = bidx; }
    __syncthreads();

    if (t == 0) {
        best = swe[0]; bidx = swi[0];
        #pragma unroll
        for (int w = 1; w < 8; w++) {
            float ov = swe[w]; int oi = swi[w];
            if (ov > best || (ov == best && oi < bidx)) { best = ov; bidx = oi; }
        }
        s_idx = bidx;
        atomicAdd(&g_counts[bidx], 1);
        long long ioff = (long long)NUM_ROWS * DIM_D + row;
        if (ioff < out_elems) out[ioff] = (float)bidx;
    }
    __syncthreads();

    const int idx = s_idx;
    // embeddings row = primitives[idx] exactly (hard one-hot forward)
    float4 v = ((const float4*)(prim + (size_t)idx * DIM_D))[t];
    ((float4*)(out + (size_t)row * DIM_D))[t] = v;
}

__global__ void vybn_counts_kernel(float* __restrict__ out, long long out_elems) {
    int k = threadIdx.x + blockIdx.x * blockDim.x;
    if (k < NUM_K) {
        long long off = (long long)NUM_ROWS * DIM_D + NUM_ROWS + k;
        if (off < out_elems) out[off] = (float)g_counts[k];
    }
}

extern "C" void kernel_launch(void* const* d_in, const int* in_sizes, int n_in,
                              void* d_out, int out_size) {
    const float* logits = (const float*)d_in[0];
    const float* prim   = (const float*)d_in[1];
    if (n_in >= 2 && in_sizes[0] < in_sizes[1]) {
        const float* tmp = logits; logits = prim; prim = tmp;
    }
    float* out = (float*)d_out;

    void* cptr = nullptr;
    cudaGetSymbolAddress(&cptr, g_counts);
    cudaMemsetAsync(cptr, 0, sizeof(int) * NUM_K, 0);

    vybn_fused_kernel<<<NUM_ROWS, 256>>>(logits, prim, out, (long long)out_size);
    vybn_counts_kernel<<<1, NUM_K>>>(out, (long long)out_size);
}

// round 6
// speedup vs baseline: 1.5780x; 1.5720x over previous
#include <cuda_runtime.h>
#include <cstdint>
#include <math.h>

// Problem constants (fixed by the reference)
#define NUM_K    1024      // primitives / codebook size
#define NUM_ROWS 32768     // 8 * 4096 tokens
#define DIM_D    1024      // embedding dim

#define TINY_F   1.17549435e-38f
#define LN2_F    0.693147180559945f
#define T_SMALL  4e-3f     // below this, MUFU relative error on t blows up -> exact path
#define CAND_EPS 3e-4f     // >3x proven |z_approx - z_exact| bound with margin
#define NEG_INF  __int_as_float(0xff800000)

// scratch: activation counts (zeroed via cudaMemsetAsync each launch)
__device__ int g_counts[NUM_K];

// ---------------------------------------------------------------------------
// Threefry-2x32, 20 rounds, key = (0, 42) (jax.random.key(42)).
// Partitionable-mode 32-bit harvest: counter=(0, elem_idx); out = x0 ^ x1.
// ---------------------------------------------------------------------------
__device__ __forceinline__ uint32_t tf_rotl(uint32_t x, int r) {
    return (x << r) | (x >> (32 - r));
}

__device__ __forceinline__ uint32_t threefry_xor(uint32_t c1) {
    const uint32_t ks0 = 0u;
    const uint32_t ks1 = 42u;
    const uint32_t ks2 = 0x1BD11BDAu ^ 0u ^ 42u;
    uint32_t x0 = 0u + ks0;
    uint32_t x1 = c1 + ks1;
#define TF_R(r) { x0 += x1; x1 = tf_rotl(x1, (r)); x1 ^= x0; }
    TF_R(13) TF_R(15) TF_R(26) TF_R(6)
    x0 += ks1; x1 += ks2 + 1u;
    TF_R(17) TF_R(29) TF_R(16) TF_R(24)
    x0 += ks2; x1 += ks0 + 2u;
    TF_R(13) TF_R(15) TF_R(26) TF_R(6)
    x0 += ks0; x1 += ks1 + 3u;
    TF_R(17) TF_R(29) TF_R(16) TF_R(24)
    x0 += ks1; x1 += ks2 + 4u;
    TF_R(13) TF_R(15) TF_R(26) TF_R(6)
    x0 += ks2; x1 += ks0 + 5u;
#undef TF_R
    return x0 ^ x1;
}

// Exact gumbel: identical formula/precision to the reference (XLA lowers log ->
// libdevice logf = CUDA accurate logf). u must already be clamped.
__device__ __forceinline__ float gumbel_exact(float u) {
    return -logf(-logf(u));
}

// ---------------------------------------------------------------------------
// One block per row. (R3 structure; launch_bounds relaxed to avoid the 32-reg
// squeeze ptxas applied at minBlocks=4, which spilled u[]/za[] and inflated
// the dynamic instruction stream by ~50%.)
// Phase 1: cheap MUFU-based z~ for all K (rare tiny-t elems take the exact
//          path inline, so their z~ carries zero error). Block max of z~.
// Phase 2: exact z (accurate logf) only for candidates within CAND_EPS of the
//          max; argmax over exact values (lower-index tie-break).
// Then gather primitives[idx] -> out, atomic count.
// ---------------------------------------------------------------------------
__global__ __launch_bounds__(256, 2)
void vybn_fused_kernel(const float* __restrict__ logits,
                       const float* __restrict__ prim,
                       float* __restrict__ out,
                       long long out_elems) {
    const int row  = blockIdx.x;
    const int t    = threadIdx.x;
    const int lane = t & 31;
    const int warp = t >> 5;

    // each thread handles k in [4t, 4t+4)
    const float4 lv = ((const float4*)(logits + (size_t)row * NUM_K))[t];
    const float lvi[4] = {lv.x, lv.y, lv.z, lv.w};
    const uint32_t base = (uint32_t)row * (uint32_t)NUM_K + (uint32_t)(4 * t);

    float u[4];   // clamped uniform, kept for the exact rescue path
    float za[4];  // z approx (exact for tiny-t elements)
    float zmax = NEG_INF;

    #pragma unroll
    for (int i = 0; i < 4; i++) {
        uint32_t bits = threefry_xor(base + (uint32_t)i);
        float f = __uint_as_float((bits >> 9) | 0x3f800000u) - 1.0f;
        u[i] = fmaxf(f, TINY_F);
        // t~ = -ln(u) = log2(u) * (-ln2)   (MUFU.LG2 + FMUL)
        float tt = __log2f(u[i]) * (-LN2_F);
        float z;
        if (tt < T_SMALL) {
            // MUFU relative error too large here (u near 1) -> exact now,
            // so z~ carries zero error for these elements.
            z = lvi[i] + gumbel_exact(u[i]);
        } else {
            // g~ = -ln(t~); z~ = fma(log2(t~), -ln2, logit)
            z = fmaf(__log2f(tt), -LN2_F, lvi[i]);
        }
        za[i] = z;
        zmax = fmaxf(zmax, z);
    }

    // block max of z~ (values only)
    #pragma unroll
    for (int off = 16; off > 0; off >>= 1)
        zmax = fmaxf(zmax, __shfl_xor_sync(0xFFFFFFFFu, zmax, off));

    __shared__ float swv[8];
    __shared__ float swe[8];
    __shared__ int   swi[8];
    __shared__ int   s_idx;
    if (lane == 0) swv[warp] = zmax;
    __syncthreads();

    float gmax = swv[0];
    #pragma unroll
    for (int w = 1; w < 8; w++) gmax = fmaxf(gmax, swv[w]);
    const float thresh = gmax - CAND_EPS;

    // Phase 2: exact evaluation for candidates only
    float best = NEG_INF;
    int   bidx = 4 * t;
    #pragma unroll
    for (int i = 0; i < 4; i++) {
        if (za[i] >= thresh) {
            float ze = lvi[i] + gumbel_exact(u[i]);
            if (ze > best) { best = ze; bidx = 4 * t + i; }
        }
    }

    // warp argmax (ties -> lower index)
    #pragma unroll
    for (int off = 16; off > 0; off >>= 1) {
        float ov = __shfl_down_sync(0xFFFFFFFFu, best, off);
        int   oi = __shfl_down_sync(0xFFFFFFFFu, bidx, off);
        if (ov > best || (ov == best && oi < bidx)) { best = ov; bidx = oi; }
    }
    if (lane == 0) { swe[warp] = best; swi[warp] = bidx; }
    __syncthreads();

    if (t == 0) {
        best = swe[0]; bidx = swi[0];
        #pragma unroll
        for (int w = 1; w < 8; w++) {
            float ov = swe[w]; int oi = swi[w];
            if (ov > best || (ov == best && oi < bidx)) { best = ov; bidx = oi; }
        }
        s_idx = bidx;
        atomicAdd(&g_counts[bidx], 1);
        long long ioff = (long long)NUM_ROWS * DIM_D + row;
        if (ioff < out_elems) out[ioff] = (float)bidx;
    }
    __syncthreads();

    const int idx = s_idx;
    // embeddings row = primitives[idx] exactly (hard one-hot forward)
    float4 v = ((const float4*)(prim + (size_t)idx * DIM_D))[t];
    ((float4*)(out + (size_t)row * DIM_D))[t] = v;
}

__global__ void vybn_counts_kernel(float* __restrict__ out, long long out_elems) {
    int k = threadIdx.x + blockIdx.x * blockDim.x;
    if (k < NUM_K) {
        long long off = (long long)NUM_ROWS * DIM_D + NUM_ROWS + k;
        if (off < out_elems) out[off] = (float)g_counts[k];
    }
}

extern "C" void kernel_launch(void* const* d_in, const int* in_sizes, int n_in,
                              void* d_out, int out_size) {
    const float* logits = (const float*)d_in[0];
    const float* prim   = (const float*)d_in[1];
    if (n_in >= 2 && in_sizes[0] < in_sizes[1]) {
        const float* tmp = logits; logits = prim; prim = tmp;
    }
    float* out = (float*)d_out;

    void* cptr = nullptr;
    cudaGetSymbolAddress(&cptr, g_counts);
    cudaMemsetAsync(cptr, 0, sizeof(int) * NUM_K, 0);

    vybn_fused_kernel<<<NUM_ROWS, 256>>>(logits, prim, out, (long long)out_size);
    vybn_counts_kernel<<<1, NUM_K>>>(out, (long long)out_size);
}